// round 2
// baseline (speedup 1.0000x reference)
#include <cuda_runtime.h>
#include <cuda_bf16.h>

// Problem constants
#define B_TOT   4096
#define T_      64
#define D_      250
#define K_      1000     // (3 stack + 1 buffer) * D
#define H_      125
#define NT      4
#define NL      50

// Tiling
#define BM      32
#define BN      128      // one MLP half per CTA (cols 0..124 valid, 125..127 pad)
#define BK      50       // divides 250 -> each K-tile stays within one gathered slot
#define NKT     (K_ / BK)
#define THREADS 256
#define XSS     52       // padded Xs row stride (floats)

__global__ __launch_bounds__(THREADS, 3)
void fused_parser_kernel(const float* __restrict__ lstm_out,
                         const int*   __restrict__ stack_index,
                         const int*   __restrict__ stack_len,
                         const int*   __restrict__ buffer_index,
                         const int*   __restrict__ buffer_len,
                         const float* __restrict__ W1t,
                         const float* __restrict__ b1t,
                         const float* __restrict__ W2t,
                         const float* __restrict__ b2t,
                         const float* __restrict__ W1r,
                         const float* __restrict__ b1r,
                         const float* __restrict__ W2r,
                         const float* __restrict__ b2r,
                         float* __restrict__ out)
{
    __shared__ float Xs[BM * XSS];        // [32][52]
    __shared__ float Ws[BK * BN];         // [50][128]  (reused as Hs [32][128] in epilogue)
    __shared__ int   soff[BM * 4];

    const int tid  = threadIdx.x;
    const int b0   = blockIdx.x * BM;
    const int half = blockIdx.y;          // 0 = transitions MLP, 1 = relations MLP

    const float* W1 = half ? W1r : W1t;

    // ---- Phase 0: gather offsets (one per row,slot) ----
    if (tid < BM * 4) {
        int row = tid >> 2, s = tid & 3;
        int b = b0 + row;
        int t, valid;
        if (s < 3) { valid = (s < stack_len[b]);  t = stack_index[b * 3 + s]; }
        else       { valid = (0 < buffer_len[b]); t = buffer_index[b]; }
        soff[tid] = valid ? (b * T_ + t) * D_ : -1;
    }

    // thread map for compute: lane -> W column group (broadcast-friendly X)
    const int c = tid & 31;               // cols c*4 .. c*4+3
    const int r = tid >> 5;               // rows r*4 .. r*4+3  (fixed within warp)

    // W-load map: n = tid&127 column, upper bit picks kk half
    const int wn  = tid & 127;
    const int wkh = (tid >> 7) * (BK / 2);     // 0 or 25
    const bool wvalid = (wn < H_);

    float acc[4][4];
    #pragma unroll
    for (int i = 0; i < 4; ++i)
        #pragma unroll
        for (int j = 0; j < 4; ++j) acc[i][j] = 0.f;

    for (int kt = 0; kt < NKT; ++kt) {
        const int k0   = kt * BK;
        const int slot = k0 / D_;
        const int d0   = k0 - slot * D_;

        __syncthreads();   // previous tile's compute done (and phase-0 on first iter)

        // load W tile [BK][BN]: W1 is [1000][125] row-major
        #pragma unroll 5
        for (int kk = 0; kk < BK / 2; ++kk) {
            Ws[(wkh + kk) * BN + wn] =
                wvalid ? __ldg(W1 + (k0 + wkh + kk) * H_ + wn) : 0.f;
        }

        // gather X tile [BM][BK] as float2: 32 rows * 25 float2 = 800 items
        for (int idx = tid; idx < BM * (BK / 2); idx += THREADS) {
            int row = idx / (BK / 2);
            int j   = idx - row * (BK / 2);
            int off = soff[row * 4 + slot];
            float2 v = make_float2(0.f, 0.f);
            if (off >= 0) v = *(const float2*)(lstm_out + off + d0 + 2 * j);
            *(float2*)(Xs + row * XSS + 2 * j) = v;
        }
        __syncthreads();

        // compute: 4x4 register tile; X reads broadcast within warp
        #pragma unroll 5
        for (int kk = 0; kk < BK; kk += 2) {
            float2 x0 = *(const float2*)(Xs + (r * 4 + 0) * XSS + kk);
            float2 x1 = *(const float2*)(Xs + (r * 4 + 1) * XSS + kk);
            float2 x2 = *(const float2*)(Xs + (r * 4 + 2) * XSS + kk);
            float2 x3 = *(const float2*)(Xs + (r * 4 + 3) * XSS + kk);
            float4 w0 = *(const float4*)(Ws + kk * BN + c * 4);
            float4 w1 = *(const float4*)(Ws + (kk + 1) * BN + c * 4);

            acc[0][0] += x0.x * w0.x; acc[0][1] += x0.x * w0.y;
            acc[0][2] += x0.x * w0.z; acc[0][3] += x0.x * w0.w;
            acc[1][0] += x1.x * w0.x; acc[1][1] += x1.x * w0.y;
            acc[1][2] += x1.x * w0.z; acc[1][3] += x1.x * w0.w;
            acc[2][0] += x2.x * w0.x; acc[2][1] += x2.x * w0.y;
            acc[2][2] += x2.x * w0.z; acc[2][3] += x2.x * w0.w;
            acc[3][0] += x3.x * w0.x; acc[3][1] += x3.x * w0.y;
            acc[3][2] += x3.x * w0.z; acc[3][3] += x3.x * w0.w;

            acc[0][0] += x0.y * w1.x; acc[0][1] += x0.y * w1.y;
            acc[0][2] += x0.y * w1.z; acc[0][3] += x0.y * w1.w;
            acc[1][0] += x1.y * w1.x; acc[1][1] += x1.y * w1.y;
            acc[1][2] += x1.y * w1.z; acc[1][3] += x1.y * w1.w;
            acc[2][0] += x2.y * w1.x; acc[2][1] += x2.y * w1.y;
            acc[2][2] += x2.y * w1.z; acc[2][3] += x2.y * w1.w;
            acc[3][0] += x3.y * w1.x; acc[3][1] += x3.y * w1.y;
            acc[3][2] += x3.y * w1.z; acc[3][3] += x3.y * w1.w;
        }
    }

    // ---- bias + tanh -> Hs (reuse Ws region) ----
    __syncthreads();
    float* Hs = Ws;   // [32][128]
    {
        const float* b1 = half ? b1r : b1t;
        float bv[4];
        #pragma unroll
        for (int j = 0; j < 4; ++j) {
            int n = c * 4 + j;
            bv[j] = (n < H_) ? b1[n] : 0.f;
        }
        #pragma unroll
        for (int i = 0; i < 4; ++i) {
            int row = r * 4 + i;
            #pragma unroll
            for (int j = 0; j < 4; ++j)
                Hs[row * BN + c * 4 + j] = tanhf(acc[i][j] + bv[j]);
        }
    }
    __syncthreads();

    // ---- tiny layer 2 + final tanh ----
    const int NO = half ? NL : NT;
    const float* W2 = half ? W2r : W2t;
    const float* b2 = half ? b2r : b2t;
    float* obase = half ? (out + B_TOT * NT) : out;

    for (int idx = tid; idx < BM * NO; idx += THREADS) {
        int row = idx / NO;
        int o   = idx - row * NO;
        const float* hrow = Hs + row * BN;
        float s = b2[o];
        #pragma unroll 5
        for (int k = 0; k < H_; ++k) s += hrow[k] * __ldg(W2 + k * NO + o);
        obase[(b0 + row) * NO + o] = tanhf(s);
    }
}

extern "C" void kernel_launch(void* const* d_in, const int* in_sizes, int n_in,
                              void* d_out, int out_size)
{
    const float* lstm_out     = (const float*)d_in[0];
    const int*   stack_index  = (const int*)  d_in[1];
    const int*   stack_len    = (const int*)  d_in[2];
    const int*   buffer_index = (const int*)  d_in[3];
    const int*   buffer_len   = (const int*)  d_in[4];
    const float* W1t          = (const float*)d_in[5];
    const float* b1t          = (const float*)d_in[6];
    const float* W2t          = (const float*)d_in[7];
    const float* b2t          = (const float*)d_in[8];
    const float* W1r          = (const float*)d_in[9];
    const float* b1r          = (const float*)d_in[10];
    const float* W2r          = (const float*)d_in[11];
    const float* b2r          = (const float*)d_in[12];
    float* out = (float*)d_out;

    dim3 grid(B_TOT / BM, 2);
    fused_parser_kernel<<<grid, THREADS>>>(
        lstm_out, stack_index, stack_len, buffer_index, buffer_len,
        W1t, b1t, W2t, b2t, W1r, b1r, W2r, b2r, out);
}

// round 4
// speedup vs baseline: 1.4797x; 1.4797x over previous
#include <cuda_runtime.h>
#include <cuda_bf16.h>
#include <stdint.h>

// Problem constants
#define B_TOT   4096
#define T_      64
#define D_      250
#define K_      1000
#define H_      125
#define NT      4
#define NL      50

// Tiling
#define BM      64
#define BN      128
#define KCH     64
#define NCHUNK  16       // 16*64 = 1024 (zero-padded past 1000)
#define THREADS 256
#define HSS     132      // Hs row stride (floats), de-conflicted

// smem layout (bytes)
#define OFF_SOFF 0                         // 64*4 ints = 1024
#define OFF_A    1024                      // [buf2][hi/lo] x 8192  = 32768
#define OFF_B    (OFF_A + 4*8192)          // [buf2][hi/lo] x 16384 = 65536
#define SMEM_TOTAL (OFF_B + 4*16384)       // 99328

#define SW128(x) ((x) ^ ((((uint32_t)(x)) >> 3) & 0x70))

// Pre-split, pre-swizzled W1 images: [half][hi/lo][chunk][panel(2)][8192B]
__device__ __align__(16) uint8_t g_wbf[(size_t)2 * 2 * 16 * 16384];

__device__ __forceinline__ uint32_t smem_u32(const void* p) {
    uint32_t a;
    asm("{ .reg .u64 t; cvta.to.shared.u64 t, %1; cvt.u32.u64 %0, t; }"
        : "=r"(a) : "l"(p));
    return a;
}

__device__ __forceinline__ void ldsm4(uint32_t r[4], uint32_t a) {
    asm volatile("ldmatrix.sync.aligned.m8n8.x4.shared.b16 {%0,%1,%2,%3}, [%4];"
        : "=r"(r[0]), "=r"(r[1]), "=r"(r[2]), "=r"(r[3]) : "r"(a));
}
__device__ __forceinline__ void ldsm4t(uint32_t r[4], uint32_t a) {
    asm volatile("ldmatrix.sync.aligned.m8n8.x4.trans.shared.b16 {%0,%1,%2,%3}, [%4];"
        : "=r"(r[0]), "=r"(r[1]), "=r"(r[2]), "=r"(r[3]) : "r"(a));
}
__device__ __forceinline__ void mma16816(float c[4], const uint32_t a[4],
                                         uint32_t b0, uint32_t b1) {
    asm volatile(
        "mma.sync.aligned.m16n8k16.row.col.f32.bf16.bf16.f32 "
        "{%0,%1,%2,%3}, {%4,%5,%6,%7}, {%8,%9}, {%0,%1,%2,%3};"
        : "+f"(c[0]), "+f"(c[1]), "+f"(c[2]), "+f"(c[3])
        : "r"(a[0]), "r"(a[1]), "r"(a[2]), "r"(a[3]), "r"(b0), "r"(b1));
}
__device__ __forceinline__ void cp_async16(uint32_t s, const void* g) {
    asm volatile("cp.async.cg.shared.global [%0], [%1], 16;" :: "r"(s), "l"(g) : "memory");
}
__device__ __forceinline__ void cp_commit() {
    asm volatile("cp.async.commit_group;" ::: "memory");
}
template <int N> __device__ __forceinline__ void cp_wait() {
    asm volatile("cp.async.wait_group %0;" :: "n"(N) : "memory");
}

// ---------------- prep kernel: split W1t/W1r into swizzled bf16 hi/lo images ----
__global__ void prep_w_kernel(const float* __restrict__ W1t,
                              const float* __restrict__ W1r)
{
    int idx  = blockIdx.x * blockDim.x + threadIdx.x;   // 0..131071
    int np   = idx & 63;            // n-pair
    int k    = (idx >> 6) & 1023;
    int half = idx >> 16;
    const float* W1 = half ? W1r : W1t;

    int n0 = np * 2;
    float w0 = 0.f, w1 = 0.f;
    if (k < K_) {
        if (n0 < H_)     w0 = W1[k * H_ + n0];
        if (n0 + 1 < H_) w1 = W1[k * H_ + n0 + 1];
    }
    __nv_bfloat16 h0 = __float2bfloat16(w0);
    __nv_bfloat16 h1 = __float2bfloat16(w1);
    __nv_bfloat16 l0 = __float2bfloat16(w0 - __bfloat162float(h0));
    __nv_bfloat16 l1 = __float2bfloat16(w1 - __bfloat162float(h1));

    int chunk = k >> 6, kloc = k & 63;
    int panel = n0 >> 6, nloc = n0 & 63;
    uint32_t sw = SW128((uint32_t)(kloc * 128 + nloc * 2));
    size_t ohi = ((size_t)(half * 2 + 0) * 16 + chunk) * 16384 + panel * 8192 + sw;
    size_t olo = ((size_t)(half * 2 + 1) * 16 + chunk) * 16384 + panel * 8192 + sw;

    *(__nv_bfloat162*)(g_wbf + ohi) = __halves2bfloat162(h0, h1);
    *(__nv_bfloat162*)(g_wbf + olo) = __halves2bfloat162(l0, l1);
}

// ---------------- main kernel --------------------------------------------------
__global__ __launch_bounds__(THREADS, 1)
void parser_hmma_kernel(const float* __restrict__ lstm_out,
                        const int*   __restrict__ stack_index,
                        const int*   __restrict__ stack_len,
                        const int*   __restrict__ buffer_index,
                        const int*   __restrict__ buffer_len,
                        const float* __restrict__ b1t,
                        const float* __restrict__ W2t,
                        const float* __restrict__ b2t,
                        const float* __restrict__ b1r,
                        const float* __restrict__ W2r,
                        const float* __restrict__ b2r,
                        float* __restrict__ out)
{
    extern __shared__ char smem[];
    const uint32_t sb = smem_u32(smem);
    const int tid  = threadIdx.x;
    const int wid  = tid >> 5;
    const int lane = tid & 31;
    const int wm   = wid & 1;          // M warp (2)
    const int wn   = wid >> 1;         // N warp (4)
    const int b0   = blockIdx.x * BM;
    const int half = blockIdx.y;

    int* soff = (int*)(smem + OFF_SOFF);

    // gather offsets: 64 rows x 4 slots
    if (tid < BM * 4) {
        int row = tid >> 2, s = tid & 3;
        int b = b0 + row;
        int t, valid;
        if (s < 3) { valid = (s < stack_len[b]);  t = stack_index[b * 3 + s]; }
        else       { valid = (0 < buffer_len[b]); t = buffer_index[b]; }
        soff[tid] = valid ? (b * T_ + t) * D_ : -1;
    }
    __syncthreads();

    // per-lane ldmatrix geometry
    const int g = lane >> 3, r8 = lane & 7;
    const int arow  = wm * 32 + (g & 1) * 8 + r8;   // + i*16
    const int acolk = (g >> 1) * 8;                 // + kb
    const int brow  = (g & 1) * 8 + r8;             // + kb
    const int bcol  = ((wn * 32) & 63) + (g >> 1) * 8;  // + j2*16
    const uint32_t bpanel = (uint32_t)(wn >> 1) * 8192;

    float acc[2][4][4];
    #pragma unroll
    for (int i = 0; i < 2; ++i)
        #pragma unroll
        for (int j = 0; j < 4; ++j)
            #pragma unroll
            for (int e = 0; e < 4; ++e) acc[i][j][e] = 0.f;

    // ---- fill helpers (inlined via lambdas) ----
    auto fillB = [&](int c) {
        int buf = c & 1;
        uint32_t dh = sb + OFF_B + (buf * 2 + 0) * 16384;
        uint32_t dl = sb + OFF_B + (buf * 2 + 1) * 16384;
        const uint8_t* sh = g_wbf + ((size_t)(half * 2 + 0) * 16 + c) * 16384;
        const uint8_t* sl = g_wbf + ((size_t)(half * 2 + 1) * 16 + c) * 16384;
        #pragma unroll
        for (int it = 0; it < 4; ++it) {
            int o = (it * THREADS + tid) * 16;
            cp_async16(dh + o, sh + o);
            cp_async16(dl + o, sl + o);
        }
        cp_commit();
    };
    auto fillA = [&](int c) {
        int buf = c & 1;
        char* ah = smem + OFF_A + (buf * 2 + 0) * 8192;
        char* al = smem + OFF_A + (buf * 2 + 1) * 8192;
        int k0 = c * KCH;
        #pragma unroll
        for (int it = 0; it < 8; ++it) {
            int idx = it * THREADS + tid;
            int kp = idx & 31, m = idx >> 5;
            int k = k0 + 2 * kp;
            float2 v = make_float2(0.f, 0.f);
            if (k < K_) {
                int slot = k / D_;
                int d    = k - slot * D_;
                int off  = soff[m * 4 + slot];
                if (off >= 0) v = *(const float2*)(lstm_out + off + d);
            }
            __nv_bfloat16 hx = __float2bfloat16(v.x);
            __nv_bfloat16 hy = __float2bfloat16(v.y);
            __nv_bfloat16 lx = __float2bfloat16(v.x - __bfloat162float(hx));
            __nv_bfloat16 ly = __float2bfloat16(v.y - __bfloat162float(hy));
            uint32_t sw = SW128((uint32_t)(m * 128 + kp * 4));
            *(__nv_bfloat162*)(ah + sw) = __halves2bfloat162(hx, hy);
            *(__nv_bfloat162*)(al + sw) = __halves2bfloat162(lx, ly);
        }
    };

    // preamble
    fillB(0);
    fillA(0);

    for (int c = 0; c < NCHUNK; ++c) {
        if (c + 1 < NCHUNK) { fillB(c + 1); fillA(c + 1); }
        if (c + 1 < NCHUNK) cp_wait<1>(); else cp_wait<0>();
        __syncthreads();

        // compute chunk c
        {
            int buf = c & 1;
            uint32_t ah = sb + OFF_A + (buf * 2 + 0) * 8192;
            uint32_t al = ah + 8192;
            uint32_t bh = sb + OFF_B + (buf * 2 + 0) * 16384 + bpanel;
            uint32_t bl = sb + OFF_B + (buf * 2 + 1) * 16384 + bpanel;

            #pragma unroll
            for (int ks = 0; ks < 4; ++ks) {
                const int kb = ks * 16;
                uint32_t Ah[2][4], Al[2][4], Bh[2][4], Bl[2][4];
                #pragma unroll
                for (int i = 0; i < 2; ++i) {
                    uint32_t off = SW128((uint32_t)((arow + i * 16) * 128 + (kb + acolk) * 2));
                    ldsm4(Ah[i], ah + off);
                    ldsm4(Al[i], al + off);
                }
                #pragma unroll
                for (int j2 = 0; j2 < 2; ++j2) {
                    uint32_t off = SW128((uint32_t)((kb + brow) * 128 + (bcol + j2 * 16) * 2));
                    ldsm4t(Bh[j2], bh + off);
                    ldsm4t(Bl[j2], bl + off);
                }
                #pragma unroll
                for (int i = 0; i < 2; ++i)
                    #pragma unroll
                    for (int j = 0; j < 4; ++j) {
                        int j2 = j >> 1, pp = (j & 1) * 2;
                        mma16816(acc[i][j], Ah[i], Bh[j2][pp], Bh[j2][pp + 1]);
                        mma16816(acc[i][j], Ah[i], Bl[j2][pp], Bl[j2][pp + 1]);
                        mma16816(acc[i][j], Al[i], Bh[j2][pp], Bh[j2][pp + 1]);
                    }
            }
        }
        __syncthreads();
    }

    // ---- epilogue: fragments -> bias + tanh -> Hs ----
    const float* b1 = half ? b1r : b1t;
    float* Hs = (float*)(smem + OFF_B);   // [64][HSS]
    #pragma unroll
    for (int i = 0; i < 2; ++i)
        #pragma unroll
        for (int j = 0; j < 4; ++j) {
            int row = wm * 32 + i * 16 + (lane >> 2);
            int col = wn * 32 + j * 8 + (lane & 3) * 2;
            float bv0 = (col < H_)     ? b1[col]     : 0.f;
            float bv1 = (col + 1 < H_) ? b1[col + 1] : 0.f;
            Hs[row * HSS + col]           = tanhf(acc[i][j][0] + bv0);
            Hs[row * HSS + col + 1]       = tanhf(acc[i][j][1] + bv1);
            Hs[(row + 8) * HSS + col]     = tanhf(acc[i][j][2] + bv0);
            Hs[(row + 8) * HSS + col + 1] = tanhf(acc[i][j][3] + bv1);
        }
    __syncthreads();

    // ---- tiny layer 2 + final tanh ----
    const int NO = half ? NL : NT;
    const float* W2 = half ? W2r : W2t;
    const float* b2 = half ? b2r : b2t;
    float* obase = half ? (out + B_TOT * NT) : out;

    for (int idx = tid; idx < BM * NO; idx += THREADS) {
        int row = idx / NO;
        int o   = idx - row * NO;
        const float* hrow = Hs + row * HSS;
        float s = __ldg(b2 + o);
        #pragma unroll 5
        for (int k = 0; k < H_; ++k) s += hrow[k] * __ldg(W2 + k * NO + o);
        obase[(b0 + row) * NO + o] = tanhf(s);
    }
}

extern "C" void kernel_launch(void* const* d_in, const int* in_sizes, int n_in,
                              void* d_out, int out_size)
{
    const float* lstm_out     = (const float*)d_in[0];
    const int*   stack_index  = (const int*)  d_in[1];
    const int*   stack_len    = (const int*)  d_in[2];
    const int*   buffer_index = (const int*)  d_in[3];
    const int*   buffer_len   = (const int*)  d_in[4];
    const float* W1t          = (const float*)d_in[5];
    const float* b1t          = (const float*)d_in[6];
    const float* W2t          = (const float*)d_in[7];
    const float* b2t          = (const float*)d_in[8];
    const float* W1r          = (const float*)d_in[9];
    const float* b1r          = (const float*)d_in[10];
    const float* W2r          = (const float*)d_in[11];
    const float* b2r          = (const float*)d_in[12];
    float* out = (float*)d_out;

    // 1) split + swizzle W1 into device-global images
    prep_w_kernel<<<512, 256>>>(W1t, W1r);

    // 2) fused gather + HMMA GEMM + MLP
    cudaFuncSetAttribute(parser_hmma_kernel,
                         cudaFuncAttributeMaxDynamicSharedMemorySize, SMEM_TOTAL);
    dim3 grid(B_TOT / BM, 2);
    parser_hmma_kernel<<<grid, THREADS, SMEM_TOTAL>>>(
        lstm_out, stack_index, stack_len, buffer_index, buffer_len,
        b1t, W2t, b2t, b1r, W2r, b2r, out);
}

// round 5
// speedup vs baseline: 1.9846x; 1.3412x over previous
#include <cuda_runtime.h>
#include <cuda_bf16.h>
#include <stdint.h>

// Problem constants
#define B_TOT   4096
#define T_      64
#define D_      250
#define K_      1000
#define H_      125
#define NT      4
#define NL      50

// Tiling
#define BM      32
#define BN      128
#define KCH     64
#define NCHUNK  16       // 16*64 = 1024 (zero-padded past 1000)
#define THREADS 256
#define HSS     132      // Hs row stride (floats)

// smem layout (bytes)
#define OFF_SOFF 0                          // 32*4 ints = 512
#define OFF_A    1024                       // [buf2][hi/lo] x 4096  = 16384
#define OFF_B    (OFF_A + 4*4096)           // [buf2][hi/lo] x 16384 = 65536
#define SMEM_TOTAL (OFF_B + 4*16384)        // 82944

#define SW128(x) ((x) ^ ((((uint32_t)(x)) >> 3) & 0x70))

// Pre-split, pre-swizzled W1 images: [half][hi/lo][chunk][panel(2)][8192B]
__device__ __align__(16) uint8_t g_wbf[(size_t)2 * 2 * 16 * 16384];

__device__ __forceinline__ uint32_t smem_u32(const void* p) {
    uint32_t a;
    asm("{ .reg .u64 t; cvta.to.shared.u64 t, %1; cvt.u32.u64 %0, t; }"
        : "=r"(a) : "l"(p));
    return a;
}

__device__ __forceinline__ void ldsm4(uint32_t r[4], uint32_t a) {
    asm volatile("ldmatrix.sync.aligned.m8n8.x4.shared.b16 {%0,%1,%2,%3}, [%4];"
        : "=r"(r[0]), "=r"(r[1]), "=r"(r[2]), "=r"(r[3]) : "r"(a));
}
__device__ __forceinline__ void ldsm4t(uint32_t r[4], uint32_t a) {
    asm volatile("ldmatrix.sync.aligned.m8n8.x4.trans.shared.b16 {%0,%1,%2,%3}, [%4];"
        : "=r"(r[0]), "=r"(r[1]), "=r"(r[2]), "=r"(r[3]) : "r"(a));
}
__device__ __forceinline__ void mma16816(float c[4], const uint32_t a[4],
                                         uint32_t b0, uint32_t b1) {
    asm volatile(
        "mma.sync.aligned.m16n8k16.row.col.f32.bf16.bf16.f32 "
        "{%0,%1,%2,%3}, {%4,%5,%6,%7}, {%8,%9}, {%0,%1,%2,%3};"
        : "+f"(c[0]), "+f"(c[1]), "+f"(c[2]), "+f"(c[3])
        : "r"(a[0]), "r"(a[1]), "r"(a[2]), "r"(a[3]), "r"(b0), "r"(b1));
}
__device__ __forceinline__ void cp_async16(uint32_t s, const void* g) {
    asm volatile("cp.async.cg.shared.global [%0], [%1], 16;" :: "r"(s), "l"(g) : "memory");
}
__device__ __forceinline__ void cp_commit() {
    asm volatile("cp.async.commit_group;" ::: "memory");
}
template <int N> __device__ __forceinline__ void cp_wait() {
    asm volatile("cp.async.wait_group %0;" :: "n"(N) : "memory");
}

// ---------------- prep kernel: split W1t/W1r into swizzled bf16 hi/lo images ----
__global__ void prep_w_kernel(const float* __restrict__ W1t,
                              const float* __restrict__ W1r)
{
    int idx  = blockIdx.x * blockDim.x + threadIdx.x;   // 0..131071
    int np   = idx & 63;            // n-pair
    int k    = (idx >> 6) & 1023;
    int half = idx >> 16;
    const float* W1 = half ? W1r : W1t;

    int n0 = np * 2;
    float w0 = 0.f, w1 = 0.f;
    if (k < K_) {
        if (n0 < H_)     w0 = W1[k * H_ + n0];
        if (n0 + 1 < H_) w1 = W1[k * H_ + n0 + 1];
    }
    __nv_bfloat16 h0 = __float2bfloat16(w0);
    __nv_bfloat16 h1 = __float2bfloat16(w1);
    __nv_bfloat16 l0 = __float2bfloat16(w0 - __bfloat162float(h0));
    __nv_bfloat16 l1 = __float2bfloat16(w1 - __bfloat162float(h1));

    int chunk = k >> 6, kloc = k & 63;
    int panel = n0 >> 6, nloc = n0 & 63;
    uint32_t sw = SW128((uint32_t)(kloc * 128 + nloc * 2));
    size_t ohi = ((size_t)(half * 2 + 0) * 16 + chunk) * 16384 + panel * 8192 + sw;
    size_t olo = ((size_t)(half * 2 + 1) * 16 + chunk) * 16384 + panel * 8192 + sw;

    *(__nv_bfloat162*)(g_wbf + ohi) = __halves2bfloat162(h0, h1);
    *(__nv_bfloat162*)(g_wbf + olo) = __halves2bfloat162(l0, l1);
}

// ---------------- main kernel --------------------------------------------------
__global__ __launch_bounds__(THREADS, 2)
void parser_hmma_kernel(const float* __restrict__ lstm_out,
                        const int*   __restrict__ stack_index,
                        const int*   __restrict__ stack_len,
                        const int*   __restrict__ buffer_index,
                        const int*   __restrict__ buffer_len,
                        const float* __restrict__ b1t,
                        const float* __restrict__ W2t,
                        const float* __restrict__ b2t,
                        const float* __restrict__ b1r,
                        const float* __restrict__ W2r,
                        const float* __restrict__ b2r,
                        float* __restrict__ out)
{
    extern __shared__ char smem[];
    const uint32_t sb = smem_u32(smem);
    const int tid  = threadIdx.x;
    const int wid  = tid >> 5;
    const int lane = tid & 31;
    const int wm   = wid & 1;          // M warp (2): rows wm*16..wm*16+15
    const int wn   = wid >> 1;         // N warp (4): cols wn*32..wn*32+31
    const int b0   = blockIdx.x * BM;
    const int half = blockIdx.y;

    int* soff = (int*)(smem + OFF_SOFF);

    // gather offsets: 32 rows x 4 slots
    if (tid < BM * 4) {
        int row = tid >> 2, s = tid & 3;
        int b = b0 + row;
        int t, valid;
        if (s < 3) { valid = (s < stack_len[b]);  t = stack_index[b * 3 + s]; }
        else       { valid = (0 < buffer_len[b]); t = buffer_index[b]; }
        soff[tid] = valid ? (b * T_ + t) * D_ : -1;
    }
    __syncthreads();

    // per-lane ldmatrix geometry
    const int g = lane >> 3, r8 = lane & 7;
    const int arow  = wm * 16 + (g & 1) * 8 + r8;
    const int acolk = (g >> 1) * 8;                      // + kb
    const int brow  = (g & 1) * 8 + r8;                  // + kb
    const int bcol  = ((wn * 32) & 63) + (g >> 1) * 8;   // + j2*16
    const uint32_t bpanel = (uint32_t)(wn >> 1) * 8192;

    float acc[4][4];
    #pragma unroll
    for (int j = 0; j < 4; ++j)
        #pragma unroll
        for (int e = 0; e < 4; ++e) acc[j][e] = 0.f;

    auto fillB = [&](int c) {
        int buf = c & 1;
        uint32_t dh = sb + OFF_B + (buf * 2 + 0) * 16384;
        uint32_t dl = sb + OFF_B + (buf * 2 + 1) * 16384;
        const uint8_t* sh = g_wbf + ((size_t)(half * 2 + 0) * 16 + c) * 16384;
        const uint8_t* sl = g_wbf + ((size_t)(half * 2 + 1) * 16 + c) * 16384;
        #pragma unroll
        for (int it = 0; it < 4; ++it) {
            int o = (it * THREADS + tid) * 16;
            cp_async16(dh + o, sh + o);
            cp_async16(dl + o, sl + o);
        }
        cp_commit();
    };
    auto fillA = [&](int c) {
        int buf = c & 1;
        char* ah = smem + OFF_A + (buf * 2 + 0) * 4096;
        char* al = smem + OFF_A + (buf * 2 + 1) * 4096;
        int k0 = c * KCH;
        #pragma unroll
        for (int it = 0; it < 4; ++it) {
            int idx = it * THREADS + tid;
            int kp = idx & 31, m = idx >> 5;
            int k = k0 + 2 * kp;
            float2 v = make_float2(0.f, 0.f);
            if (k < K_) {
                int slot = k / D_;
                int d    = k - slot * D_;
                int off  = soff[m * 4 + slot];
                if (off >= 0) v = *(const float2*)(lstm_out + off + d);
            }
            __nv_bfloat16 hx = __float2bfloat16(v.x);
            __nv_bfloat16 hy = __float2bfloat16(v.y);
            __nv_bfloat16 lx = __float2bfloat16(v.x - __bfloat162float(hx));
            __nv_bfloat16 ly = __float2bfloat16(v.y - __bfloat162float(hy));
            uint32_t sw = SW128((uint32_t)(m * 128 + kp * 4));
            *(__nv_bfloat162*)(ah + sw) = __halves2bfloat162(hx, hy);
            *(__nv_bfloat162*)(al + sw) = __halves2bfloat162(lx, ly);
        }
    };

    // preamble
    fillB(0);
    fillA(0);

    for (int c = 0; c < NCHUNK; ++c) {
        if (c + 1 < NCHUNK) { fillB(c + 1); fillA(c + 1); }
        if (c + 1 < NCHUNK) cp_wait<1>(); else cp_wait<0>();
        __syncthreads();

        // compute chunk c
        {
            int buf = c & 1;
            uint32_t ah = sb + OFF_A + (buf * 2 + 0) * 4096;
            uint32_t al = ah + 4096;
            uint32_t bh = sb + OFF_B + (buf * 2 + 0) * 16384 + bpanel;
            uint32_t bl = sb + OFF_B + (buf * 2 + 1) * 16384 + bpanel;

            #pragma unroll
            for (int ks = 0; ks < 4; ++ks) {
                const int kb = ks * 16;
                uint32_t Ah[4], Al[4], Bh[2][4], Bl[2][4];
                {
                    uint32_t off = SW128((uint32_t)(arow * 128 + (kb + acolk) * 2));
                    ldsm4(Ah, ah + off);
                    ldsm4(Al, al + off);
                }
                #pragma unroll
                for (int j2 = 0; j2 < 2; ++j2) {
                    uint32_t off = SW128((uint32_t)((kb + brow) * 128 + (bcol + j2 * 16) * 2));
                    ldsm4t(Bh[j2], bh + off);
                    ldsm4t(Bl[j2], bl + off);
                }
                // pass-major order: breaks RAW chains on accumulators
                #pragma unroll
                for (int j = 0; j < 4; ++j) {
                    int j2 = j >> 1, pp = (j & 1) * 2;
                    mma16816(acc[j], Ah, Bh[j2][pp], Bh[j2][pp + 1]);
                }
                #pragma unroll
                for (int j = 0; j < 4; ++j) {
                    int j2 = j >> 1, pp = (j & 1) * 2;
                    mma16816(acc[j], Ah, Bl[j2][pp], Bl[j2][pp + 1]);
                }
                #pragma unroll
                for (int j = 0; j < 4; ++j) {
                    int j2 = j >> 1, pp = (j & 1) * 2;
                    mma16816(acc[j], Al, Bh[j2][pp], Bh[j2][pp + 1]);
                }
            }
        }
        __syncthreads();
    }

    // ---- epilogue: fragments -> bias + tanh -> Hs ----
    const float* b1 = half ? b1r : b1t;
    float* Hs = (float*)(smem + OFF_B);   // [32][HSS]
    #pragma unroll
    for (int j = 0; j < 4; ++j) {
        int row = wm * 16 + (lane >> 2);
        int col = wn * 32 + j * 8 + (lane & 3) * 2;
        float bv0 = (col < H_)     ? b1[col]     : 0.f;
        float bv1 = (col + 1 < H_) ? b1[col + 1] : 0.f;
        Hs[row * HSS + col]           = tanhf(acc[j][0] + bv0);
        Hs[row * HSS + col + 1]       = tanhf(acc[j][1] + bv1);
        Hs[(row + 8) * HSS + col]     = tanhf(acc[j][2] + bv0);
        Hs[(row + 8) * HSS + col + 1] = tanhf(acc[j][3] + bv1);
    }
    __syncthreads();

    // ---- tiny layer 2 + final tanh ----
    const int NO = half ? NL : NT;
    const float* W2 = half ? W2r : W2t;
    const float* b2 = half ? b2r : b2t;
    float* obase = half ? (out + B_TOT * NT) : out;

    for (int idx = tid; idx < BM * NO; idx += THREADS) {
        int row = idx / NO;
        int o   = idx - row * NO;
        const float* hrow = Hs + row * HSS;
        float s = __ldg(b2 + o);
        #pragma unroll 5
        for (int k = 0; k < H_; ++k) s += hrow[k] * __ldg(W2 + k * NO + o);
        obase[(b0 + row) * NO + o] = tanhf(s);
    }
}

extern "C" void kernel_launch(void* const* d_in, const int* in_sizes, int n_in,
                              void* d_out, int out_size)
{
    const float* lstm_out     = (const float*)d_in[0];
    const int*   stack_index  = (const int*)  d_in[1];
    const int*   stack_len    = (const int*)  d_in[2];
    const int*   buffer_index = (const int*)  d_in[3];
    const int*   buffer_len   = (const int*)  d_in[4];
    const float* W1t          = (const float*)d_in[5];
    const float* b1t          = (const float*)d_in[6];
    const float* W2t          = (const float*)d_in[7];
    const float* b2t          = (const float*)d_in[8];
    const float* W1r          = (const float*)d_in[9];
    const float* b1r          = (const float*)d_in[10];
    const float* W2r          = (const float*)d_in[11];
    const float* b2r          = (const float*)d_in[12];
    float* out = (float*)d_out;

    // 1) split + swizzle W1 into device-global images
    prep_w_kernel<<<512, 256>>>(W1t, W1r);

    // 2) fused gather + HMMA GEMM + MLP
    cudaFuncSetAttribute(parser_hmma_kernel,
                         cudaFuncAttributeMaxDynamicSharedMemorySize, SMEM_TOTAL);
    dim3 grid(B_TOT / BM, 2);
    parser_hmma_kernel<<<grid, THREADS, SMEM_TOTAL>>>(
        lstm_out, stack_index, stack_len, buffer_index, buffer_len,
        b1t, W2t, b2t, b1r, W2r, b2r, out);
}